// round 3
// baseline (speedup 1.0000x reference)
#include <cuda_runtime.h>
#include <cuda_bf16.h>
#include <cstdint>
#include <cstddef>

#define NN 2048
#define NROWS 16384   // B * N

// ---------------- device scratch (no allocations allowed) ----------------
__device__ float g_dinv[NROWS];        // rsqrt(rowsum(A)+1)
__device__ float g_M1[NROWS * 64];     // d_j * (X@W1)_j
__device__ float g_T1[NROWS * 64];     // A @ M1
__device__ float g_Pp[NROWS * 16];     // d_j * (h_drop @ W2)_j

// ---------------- packed fp32x2 helpers (sm_100+) ----------------
__device__ __forceinline__ unsigned long long ffma2(unsigned long long a,
                                                    unsigned long long b,
                                                    unsigned long long c) {
    unsigned long long d;
    asm("fma.rn.f32x2 %0, %1, %2, %3;" : "=l"(d) : "l"(a), "l"(b), "l"(c));
    return d;
}
__device__ __forceinline__ float lo32(unsigned long long v) { return __uint_as_float((unsigned)v); }
__device__ __forceinline__ float hi32(unsigned long long v) { return __uint_as_float((unsigned)(v >> 32)); }

// ---------------- exact JAX threefry2x32, key = (0, 42) ----------------
__device__ __forceinline__ unsigned tf_rotl(unsigned x, int r) { return (x << r) | (x >> (32 - r)); }
__device__ __forceinline__ void threefry(unsigned x0, unsigned x1, unsigned &o0, unsigned &o1) {
    const unsigned k0 = 0u, k1 = 42u;
    const unsigned k2 = 0x1BD11BDAu ^ k0 ^ k1;
    x0 += k0; x1 += k1;
#define RND(r) { x0 += x1; x1 = tf_rotl(x1, (r)); x1 ^= x0; }
    RND(13) RND(15) RND(26) RND(6)   x0 += k1; x1 += k2 + 1u;
    RND(17) RND(29) RND(16) RND(24)  x0 += k2; x1 += k0 + 2u;
    RND(13) RND(15) RND(26) RND(6)   x0 += k0; x1 += k1 + 3u;
    RND(17) RND(29) RND(16) RND(24)  x0 += k1; x1 += k2 + 4u;
    RND(13) RND(15) RND(26) RND(6)   x0 += k2; x1 += k0 + 5u;
#undef RND
    o0 = x0; o1 = x1;
}

// ---------------- K1: d = rsqrt(rowsum(A) + 1), one warp per row ----------------
__global__ __launch_bounds__(256) void k1_rowsum(const float* __restrict__ A) {
    int row  = blockIdx.x * 8 + (threadIdx.x >> 5);
    int lane = threadIdx.x & 31;
    const float4* p = reinterpret_cast<const float4*>(A + (size_t)row * NN);
    float s0 = 0.f, s1 = 0.f, s2 = 0.f, s3 = 0.f;
#pragma unroll
    for (int it = 0; it < 16; it += 4) {
        float4 a = p[(it + 0) * 32 + lane];
        float4 b = p[(it + 1) * 32 + lane];
        float4 c = p[(it + 2) * 32 + lane];
        float4 d = p[(it + 3) * 32 + lane];
        s0 += (a.x + a.y) + (a.z + a.w);
        s1 += (b.x + b.y) + (b.z + b.w);
        s2 += (c.x + c.y) + (c.z + c.w);
        s3 += (d.x + d.y) + (d.z + d.w);
    }
    float s = (s0 + s1) + (s2 + s3);
#pragma unroll
    for (int o = 16; o; o >>= 1) s += __shfl_xor_sync(0xffffffffu, s, o);
    if (lane == 0) g_dinv[row] = rsqrtf(s + 1.0f);
}

// ---------------- K2: M1 = d * (X @ W1), 16 rows per block ----------------
__global__ __launch_bounds__(256) void k2_xw(const float* __restrict__ X,
                                             const float* __restrict__ W1) {
    __shared__ __align__(16) float Ws[64][64];
    __shared__ float Xs[16][68];
    int tid  = threadIdx.x;
    int row0 = blockIdx.x * 16;
#pragma unroll
    for (int s = 0; s < 4; ++s) {
        int slot = tid + s * 256;
        *reinterpret_cast<float4*>(&Ws[0][0] + (size_t)slot * 4) =
            reinterpret_cast<const float4*>(W1)[slot];
    }
    {
        int r = tid >> 4, cq = tid & 15;
        float4 v = reinterpret_cast<const float4*>(X + (size_t)(row0 + r) * 64)[cq];
        Xs[r][cq * 4 + 0] = v.x; Xs[r][cq * 4 + 1] = v.y;
        Xs[r][cq * 4 + 2] = v.z; Xs[r][cq * 4 + 3] = v.w;
    }
    __syncthreads();
    int r = tid >> 4, cx = tid & 15;
    float4 acc = make_float4(0.f, 0.f, 0.f, 0.f);
#pragma unroll
    for (int k = 0; k < 64; ++k) {
        float x  = Xs[r][k];
        float4 w = *reinterpret_cast<const float4*>(&Ws[k][cx * 4]);
        acc.x = fmaf(x, w.x, acc.x);
        acc.y = fmaf(x, w.y, acc.y);
        acc.z = fmaf(x, w.z, acc.z);
        acc.w = fmaf(x, w.w, acc.w);
    }
    int grow = row0 + r;
    float d  = g_dinv[grow];
    acc.x *= d; acc.y *= d; acc.z *= d; acc.w *= d;
    reinterpret_cast<float4*>(g_M1 + (size_t)grow * 64)[cx] = acc;
}

// ---------------- K3: T1 = A @ M1 (per batch), f32x2 FMA ----------------
// Block: 128 rows x 64 cols, KT=16, double-buffered smem.
// As transposed (row pairs contiguous), Bs duplicated (col dups contiguous).
__global__ __launch_bounds__(256) void k3_gemm(const float* __restrict__ A) {
    __shared__ __align__(16) float As[2][16][132];
    __shared__ __align__(16) float Bs[2][16][128];
    const int tid  = threadIdx.x;
    const int b    = blockIdx.y;
    const int row0 = blockIdx.x << 7;
    const float* Ab = A    + ((size_t)b * NN + row0) * NN;
    const float* Bb = g_M1 + ((size_t)b * NN) * 64;
    const int cx  = tid & 15;           // 4 cols:  cx*4 .. cx*4+3
    const int ry  = tid >> 4;           // 8 rows:  ry*8 .. ry*8+7
    const int ar0 = tid >> 2;           // A loader rows ar0, ar0+64
    const int ak4 = (tid & 3) * 4;      // A loader k quad
    const int bkr = tid >> 4;           // B loader k row
    const int bc4 = (tid & 15) * 4;     // B loader col quad

    unsigned long long acc[4][4] = {};
    float4 ra0, ra1, rb;

    // tile 0 load + store
    ra0 = *reinterpret_cast<const float4*>(Ab + (size_t)ar0 * NN + ak4);
    ra1 = *reinterpret_cast<const float4*>(Ab + (size_t)(ar0 + 64) * NN + ak4);
    rb  = *reinterpret_cast<const float4*>(Bb + (size_t)bkr * 64 + bc4);
    {
        As[0][ak4 + 0][ar0] = ra0.x; As[0][ak4 + 1][ar0] = ra0.y;
        As[0][ak4 + 2][ar0] = ra0.z; As[0][ak4 + 3][ar0] = ra0.w;
        As[0][ak4 + 0][ar0 + 64] = ra1.x; As[0][ak4 + 1][ar0 + 64] = ra1.y;
        As[0][ak4 + 2][ar0 + 64] = ra1.z; As[0][ak4 + 3][ar0 + 64] = ra1.w;
        float* d0 = &Bs[0][bkr][bc4 * 2];
        reinterpret_cast<float4*>(d0)[0] = make_float4(rb.x, rb.x, rb.y, rb.y);
        reinterpret_cast<float4*>(d0)[1] = make_float4(rb.z, rb.z, rb.w, rb.w);
    }
    __syncthreads();
    int p = 0;
#pragma unroll 1
    for (int it = 0; it < 128; ++it) {
        if (it < 127) {
            int k0 = (it + 1) << 4;
            ra0 = *reinterpret_cast<const float4*>(Ab + (size_t)ar0 * NN + k0 + ak4);
            ra1 = *reinterpret_cast<const float4*>(Ab + (size_t)(ar0 + 64) * NN + k0 + ak4);
            rb  = *reinterpret_cast<const float4*>(Bb + (size_t)(k0 + bkr) * 64 + bc4);
        }
#pragma unroll
        for (int k = 0; k < 16; ++k) {
            const ulonglong2* ap = reinterpret_cast<const ulonglong2*>(&As[p][k][ry * 8]);
            const ulonglong2* bp = reinterpret_cast<const ulonglong2*>(&Bs[p][k][cx * 8]);
            ulonglong2 a01 = ap[0], a23 = ap[1];
            ulonglong2 b01 = bp[0], b23 = bp[1];
            unsigned long long av[4] = {a01.x, a01.y, a23.x, a23.y};
            unsigned long long bv[4] = {b01.x, b01.y, b23.x, b23.y};
#pragma unroll
            for (int i = 0; i < 4; ++i)
#pragma unroll
                for (int j = 0; j < 4; ++j)
                    acc[i][j] = ffma2(av[i], bv[j], acc[i][j]);
        }
        if (it < 127) {
            int q = p ^ 1;
            As[q][ak4 + 0][ar0] = ra0.x; As[q][ak4 + 1][ar0] = ra0.y;
            As[q][ak4 + 2][ar0] = ra0.z; As[q][ak4 + 3][ar0] = ra0.w;
            As[q][ak4 + 0][ar0 + 64] = ra1.x; As[q][ak4 + 1][ar0 + 64] = ra1.y;
            As[q][ak4 + 2][ar0 + 64] = ra1.z; As[q][ak4 + 3][ar0 + 64] = ra1.w;
            float* d0 = &Bs[q][bkr][bc4 * 2];
            reinterpret_cast<float4*>(d0)[0] = make_float4(rb.x, rb.x, rb.y, rb.y);
            reinterpret_cast<float4*>(d0)[1] = make_float4(rb.z, rb.z, rb.w, rb.w);
        }
        __syncthreads();
        p ^= 1;
    }
    float* C = g_T1 + ((size_t)b * NN + row0) * 64;
#pragma unroll
    for (int i = 0; i < 4; ++i) {
        int r = ry * 8 + 2 * i;
        float4 v0 = make_float4(lo32(acc[i][0]), lo32(acc[i][1]), lo32(acc[i][2]), lo32(acc[i][3]));
        float4 v1 = make_float4(hi32(acc[i][0]), hi32(acc[i][1]), hi32(acc[i][2]), hi32(acc[i][3]));
        *reinterpret_cast<float4*>(C + (size_t)r * 64 + cx * 4)       = v0;
        *reinterpret_cast<float4*>(C + (size_t)(r + 1) * 64 + cx * 4) = v1;
    }
}

// ---------------- K4: bias+relu+dropout, P' = d * (h @ W2) ----------------
// Dropout = JAX partitionable threefry: per element i (flat over (8,2048,64)):
//   (b1,b2) = threefry2x32(key=(0,42), x0=hi32(i)=0, x1=lo32(i)=i); bits = b1^b2;
//   keep <=> uniform(bits) < 0.5 <=> top bit of bits clear.
__global__ __launch_bounds__(256) void k4_act(const float* __restrict__ b1v,
                                              const float* __restrict__ W2) {
    __shared__ float hs[4][65];
    __shared__ float W2s[64][17];
    int tid = threadIdx.x;
    {
        float4 v = reinterpret_cast<const float4*>(W2)[tid];  // 1024 floats = 256 x float4
        int rr = tid >> 2, c0 = (tid & 3) * 4;
        W2s[rr][c0] = v.x; W2s[rr][c0 + 1] = v.y; W2s[rr][c0 + 2] = v.z; W2s[rr][c0 + 3] = v.w;
    }
    int rl = tid >> 6, t = tid & 63;
    int row = (blockIdx.x << 2) + rl;
    float dv  = g_dinv[row];
    float pre = dv * (g_T1[(size_t)row * 64 + t] + g_M1[(size_t)row * 64 + t]) + b1v[t];
    float h = fmaxf(pre, 0.0f);
    unsigned idx = ((unsigned)row << 6) + (unsigned)t;
    unsigned o0, o1;
    threefry(0u, idx, o0, o1);
    unsigned bits = o0 ^ o1;
    hs[rl][t] = (bits & 0x80000000u) ? 0.0f : h + h;   // keep <=> top bit clear; /0.5 = *2
    __syncthreads();
    if (tid < 64) {
        int rr = tid >> 4, c = tid & 15;
        float acc = 0.0f;
#pragma unroll
        for (int k = 0; k < 64; ++k) acc = fmaf(hs[rr][k], W2s[k][c], acc);
        int grow = (blockIdx.x << 2) + rr;
        g_Pp[(size_t)grow * 16 + c] = g_dinv[grow] * acc;
    }
}

// ---------------- K5: out = d*(A@P' + P') + b2 ----------------
// Block: 128 rows x 16 cols, same double-buffer structure as K3.
__global__ __launch_bounds__(256) void k5_out(const float* __restrict__ A,
                                              const float* __restrict__ b2,
                                              float* __restrict__ out) {
    __shared__ __align__(16) float As[2][16][132];
    __shared__ __align__(16) float Bs[2][16][32];
    const int tid  = threadIdx.x;
    const int b    = blockIdx.y;
    const int row0 = blockIdx.x << 7;
    const float* Ab = A    + ((size_t)b * NN + row0) * NN;
    const float* Pb = g_Pp + ((size_t)b * NN) * 16;
    const int cx  = tid & 7;            // 2 cols: cx*2, cx*2+1
    const int ry  = tid >> 3;           // 4 rows: ry*4 .. ry*4+3
    const int ar0 = tid >> 2;
    const int ak4 = (tid & 3) * 4;
    const int bk  = tid >> 2;           // valid when tid < 64
    const int bq4 = (tid & 3) * 4;

    unsigned long long acc[2][2] = {};
    float4 ra0, ra1, rb;

    ra0 = *reinterpret_cast<const float4*>(Ab + (size_t)ar0 * NN + ak4);
    ra1 = *reinterpret_cast<const float4*>(Ab + (size_t)(ar0 + 64) * NN + ak4);
    if (tid < 64) rb = *reinterpret_cast<const float4*>(Pb + (size_t)bk * 16 + bq4);
    {
        As[0][ak4 + 0][ar0] = ra0.x; As[0][ak4 + 1][ar0] = ra0.y;
        As[0][ak4 + 2][ar0] = ra0.z; As[0][ak4 + 3][ar0] = ra0.w;
        As[0][ak4 + 0][ar0 + 64] = ra1.x; As[0][ak4 + 1][ar0 + 64] = ra1.y;
        As[0][ak4 + 2][ar0 + 64] = ra1.z; As[0][ak4 + 3][ar0 + 64] = ra1.w;
        if (tid < 64) {
            float* d0 = &Bs[0][bk][bq4 * 2];
            reinterpret_cast<float4*>(d0)[0] = make_float4(rb.x, rb.x, rb.y, rb.y);
            reinterpret_cast<float4*>(d0)[1] = make_float4(rb.z, rb.z, rb.w, rb.w);
        }
    }
    __syncthreads();
    int p = 0;
#pragma unroll 1
    for (int it = 0; it < 128; ++it) {
        if (it < 127) {
            int k0 = (it + 1) << 4;
            ra0 = *reinterpret_cast<const float4*>(Ab + (size_t)ar0 * NN + k0 + ak4);
            ra1 = *reinterpret_cast<const float4*>(Ab + (size_t)(ar0 + 64) * NN + k0 + ak4);
            if (tid < 64) rb = *reinterpret_cast<const float4*>(Pb + (size_t)(k0 + bk) * 16 + bq4);
        }
#pragma unroll
        for (int k = 0; k < 16; ++k) {
            ulonglong2 aa = *reinterpret_cast<const ulonglong2*>(&As[p][k][ry * 4]);
            ulonglong2 bb = *reinterpret_cast<const ulonglong2*>(&Bs[p][k][cx * 4]);
            acc[0][0] = ffma2(aa.x, bb.x, acc[0][0]);
            acc[0][1] = ffma2(aa.x, bb.y, acc[0][1]);
            acc[1][0] = ffma2(aa.y, bb.x, acc[1][0]);
            acc[1][1] = ffma2(aa.y, bb.y, acc[1][1]);
        }
        if (it < 127) {
            int q = p ^ 1;
            As[q][ak4 + 0][ar0] = ra0.x; As[q][ak4 + 1][ar0] = ra0.y;
            As[q][ak4 + 2][ar0] = ra0.z; As[q][ak4 + 3][ar0] = ra0.w;
            As[q][ak4 + 0][ar0 + 64] = ra1.x; As[q][ak4 + 1][ar0 + 64] = ra1.y;
            As[q][ak4 + 2][ar0 + 64] = ra1.z; As[q][ak4 + 3][ar0 + 64] = ra1.w;
            if (tid < 64) {
                float* d0 = &Bs[q][bk][bq4 * 2];
                reinterpret_cast<float4*>(d0)[0] = make_float4(rb.x, rb.x, rb.y, rb.y);
                reinterpret_cast<float4*>(d0)[1] = make_float4(rb.z, rb.z, rb.w, rb.w);
            }
        }
        __syncthreads();
        p ^= 1;
    }
    const float* Prow = Pb + (size_t)row0 * 16;
    float* Ob = out + ((size_t)b * NN + row0) * 16;
    float bb0 = b2[cx * 2], bb1 = b2[cx * 2 + 1];
#pragma unroll
    for (int i = 0; i < 2; ++i) {
#pragma unroll
        for (int h = 0; h < 2; ++h) {
            int r = ry * 4 + 2 * i + h;
            float dv = g_dinv[(size_t)b * NN + row0 + r];
            float p0 = Prow[(size_t)r * 16 + cx * 2];
            float p1 = Prow[(size_t)r * 16 + cx * 2 + 1];
            float t0 = h ? hi32(acc[i][0]) : lo32(acc[i][0]);
            float t1 = h ? hi32(acc[i][1]) : lo32(acc[i][1]);
            float2 o;
            o.x = dv * (t0 + p0) + bb0;
            o.y = dv * (t1 + p1) + bb1;
            *reinterpret_cast<float2*>(Ob + (size_t)r * 16 + cx * 2) = o;
        }
    }
}

// ---------------- launch ----------------
extern "C" void kernel_launch(void* const* d_in, const int* in_sizes, int n_in,
                              void* d_out, int out_size) {
    const float* X  = (const float*)d_in[0];
    const float* A  = (const float*)d_in[1];
    const float* W1 = (const float*)d_in[2];
    const float* b1 = (const float*)d_in[3];
    const float* W2 = (const float*)d_in[4];
    const float* b2 = (const float*)d_in[5];
    float* out = (float*)d_out;

    k1_rowsum<<<2048, 256>>>(A);
    k2_xw<<<1024, 256>>>(X, W1);
    k3_gemm<<<dim3(16, 8), 256>>>(A);
    k4_act<<<4096, 256>>>(b1, W2);
    k5_out<<<dim3(16, 8), 256>>>(A, b2, out);
}

// round 5
// speedup vs baseline: 4.3889x; 4.3889x over previous
#include <cuda_runtime.h>
#include <cuda_bf16.h>
#include <cstdint>
#include <cstddef>

#define NN 2048
#define NROWS 16384   // B * N

// ---------------- device scratch ----------------
__device__ __align__(128) float g_dinv[NROWS];      // rsqrt(rowsum(A)+1)
__device__ __align__(128) float g_M1[NROWS * 64];   // d_j*(X@W1), row-major f32
__device__ __align__(128) float g_T1[NROWS * 64];   // A @ M1
__device__ __align__(128) float g_Pp[NROWS * 16];   // d_j*(h_drop@W2), row-major f32

// ---------------- helpers ----------------
__device__ __forceinline__ uint32_t smem_u32(const void* p) {
    uint32_t a;
    asm("{ .reg .u64 t; cvta.to.shared.u64 t, %1; cvt.u32.u64 %0, t; }" : "=r"(a) : "l"(p));
    return a;
}
__device__ __forceinline__ uint32_t cvt_tf32(float f) {
    uint32_t r;
    asm("cvt.rna.tf32.f32 %0, %1;" : "=r"(r) : "f"(f));
    return r;
}
__device__ __forceinline__ void cp16(uint32_t dst, const float* src) {
    asm volatile("cp.async.cg.shared.global [%0], [%1], 16;" :: "r"(dst), "l"(src) : "memory");
}
__device__ __forceinline__ void mma_tf32(float* c, const uint32_t* a, const uint32_t* b) {
    asm volatile("mma.sync.aligned.m16n8k8.row.col.f32.tf32.tf32.f32 "
                 "{%0,%1,%2,%3}, {%4,%5,%6,%7}, {%8,%9}, {%0,%1,%2,%3};"
                 : "+f"(c[0]), "+f"(c[1]), "+f"(c[2]), "+f"(c[3])
                 : "r"(a[0]), "r"(a[1]), "r"(a[2]), "r"(a[3]), "r"(b[0]), "r"(b[1]));
}

// ---------------- exact JAX threefry2x32 (partitionable), key = (0, 42) ----------------
__device__ __forceinline__ unsigned tf_rotl(unsigned x, int r) { return (x << r) | (x >> (32 - r)); }
__device__ __forceinline__ void threefry(unsigned x0, unsigned x1, unsigned &o0, unsigned &o1) {
    const unsigned k0 = 0u, k1 = 42u;
    const unsigned k2 = 0x1BD11BDAu ^ k0 ^ k1;
    x0 += k0; x1 += k1;
#define RND(r) { x0 += x1; x1 = tf_rotl(x1, (r)); x1 ^= x0; }
    RND(13) RND(15) RND(26) RND(6)   x0 += k1; x1 += k2 + 1u;
    RND(17) RND(29) RND(16) RND(24)  x0 += k2; x1 += k0 + 2u;
    RND(13) RND(15) RND(26) RND(6)   x0 += k0; x1 += k1 + 3u;
    RND(17) RND(29) RND(16) RND(24)  x0 += k1; x1 += k2 + 4u;
    RND(13) RND(15) RND(26) RND(6)   x0 += k2; x1 += k0 + 5u;
#undef RND
    o0 = x0; o1 = x1;
}

// ---------------- K1: d = rsqrt(rowsum(A)+1), one warp per row ----------------
__global__ __launch_bounds__(256) void k1_rowsum(const float* __restrict__ A) {
    int row  = blockIdx.x * 8 + (threadIdx.x >> 5);
    int lane = threadIdx.x & 31;
    const float4* p = reinterpret_cast<const float4*>(A + (size_t)row * NN);
    float s0 = 0.f, s1 = 0.f, s2 = 0.f, s3 = 0.f;
#pragma unroll
    for (int it = 0; it < 16; it += 4) {
        float4 a = p[(it + 0) * 32 + lane];
        float4 b = p[(it + 1) * 32 + lane];
        float4 c = p[(it + 2) * 32 + lane];
        float4 d = p[(it + 3) * 32 + lane];
        s0 += (a.x + a.y) + (a.z + a.w);
        s1 += (b.x + b.y) + (b.z + b.w);
        s2 += (c.x + c.y) + (c.z + c.w);
        s3 += (d.x + d.y) + (d.z + d.w);
    }
    float s = (s0 + s1) + (s2 + s3);
#pragma unroll
    for (int o = 16; o; o >>= 1) s += __shfl_xor_sync(0xffffffffu, s, o);
    if (lane == 0) g_dinv[row] = rsqrtf(s + 1.0f);
}

// ---------------- K2: M1 = d * (X @ W1) ----------------
__global__ __launch_bounds__(256) void k2_xw(const float* __restrict__ X,
                                             const float* __restrict__ W1) {
    __shared__ __align__(16) float Ws[64][64];
    __shared__ float Xs[16][68];
    int tid  = threadIdx.x;
    int row0 = blockIdx.x * 16;
#pragma unroll
    for (int s = 0; s < 4; ++s) {
        int slot = tid + s * 256;
        *reinterpret_cast<float4*>(&Ws[0][0] + (size_t)slot * 4) =
            reinterpret_cast<const float4*>(W1)[slot];
    }
    {
        int r = tid >> 4, cq = tid & 15;
        float4 v = reinterpret_cast<const float4*>(X + (size_t)(row0 + r) * 64)[cq];
        Xs[r][cq * 4 + 0] = v.x; Xs[r][cq * 4 + 1] = v.y;
        Xs[r][cq * 4 + 2] = v.z; Xs[r][cq * 4 + 3] = v.w;
    }
    __syncthreads();
    int r = tid >> 4, cx = tid & 15;
    float4 acc = make_float4(0.f, 0.f, 0.f, 0.f);
#pragma unroll
    for (int k = 0; k < 64; ++k) {
        float x  = Xs[r][k];
        float4 w = *reinterpret_cast<const float4*>(&Ws[k][cx * 4]);
        acc.x = fmaf(x, w.x, acc.x);
        acc.y = fmaf(x, w.y, acc.y);
        acc.z = fmaf(x, w.z, acc.z);
        acc.w = fmaf(x, w.w, acc.w);
    }
    int grow = row0 + r;
    float d  = g_dinv[grow];
    acc.x *= d; acc.y *= d; acc.z *= d; acc.w *= d;
    reinterpret_cast<float4*>(g_M1 + (size_t)grow * 64)[cx] = acc;
}

// ---------------- tf32 mma.sync GEMM: C[128 x NCOLS] = A_tile @ B ----------------
// B is row-major [2048 x NCOLS] (k-major == mma col-major fragment layout).
// FINAL=false: B=g_M1, C->g_T1.  FINAL=true: B=g_Pp, fused epilogue -> out.
template<int NCOLS, bool FINAL>
__global__ __launch_bounds__(256) void gemm_mma(const float* __restrict__ A,
                                                const float* __restrict__ b2,
                                                float* __restrict__ out) {
    constexpr int ASTR = 36;                     // A smem stride (floats)
    constexpr int BSTR = (NCOLS == 64) ? 72 : 24; // B smem stride (floats)
    constexpr int ASTAGEF = 128 * ASTR;          // 4608 floats
    constexpr int BSTAGEF = 32 * BSTR;           // 2304 / 768 floats
    extern __shared__ __align__(16) float smem[];
    float* Abase = smem;
    float* Bbase = smem + 4 * ASTAGEF;

    const int tid = threadIdx.x, wid = tid >> 5, lane = tid & 31;
    const int wm = wid & 3, wn = wid >> 2;              // warp tile: rows wm*32, cols wn*(NCOLS/2)
    const int bb = blockIdx.y, row0 = blockIdx.x << 7;
    const float* Ab = A + ((size_t)bb * NN + row0) * NN;
    const float* Bb = (FINAL ? g_Pp : g_M1) + (size_t)bb * NN * NCOLS;
    const uint32_t sb = smem_u32(smem);

    constexpr int NMMA = (NCOLS == 64) ? 4 : 1;         // n-blocks of 8 per warp
    float acc[2][NMMA][4];
#pragma unroll
    for (int i = 0; i < 2; ++i)
#pragma unroll
        for (int j = 0; j < NMMA; ++j)
#pragma unroll
            for (int q = 0; q < 4; ++q) acc[i][j][q] = 0.f;

    auto load_chunk = [&](int c, int s) {
        uint32_t ab = sb + s * (ASTAGEF * 4);
#pragma unroll
        for (int j = 0; j < 4; ++j) {
            int seg = tid + j * 256;
            int r = seg >> 3, q = seg & 7;
            cp16(ab + (uint32_t)(r * ASTR * 4 + q * 16), Ab + (size_t)r * NN + c * 32 + q * 4);
        }
        uint32_t bbs = sb + (uint32_t)(4 * ASTAGEF * 4) + s * (BSTAGEF * 4);
        if (NCOLS == 64) {
#pragma unroll
            for (int j = 0; j < 2; ++j) {
                int seg = tid + j * 256;
                int kr = seg >> 4, q = seg & 15;
                cp16(bbs + (uint32_t)(kr * BSTR * 4 + q * 16), Bb + (size_t)(c * 32 + kr) * 64 + q * 4);
            }
        } else {
            if (tid < 128) {
                int kr = tid >> 2, q = tid & 3;
                cp16(bbs + (uint32_t)(kr * BSTR * 4 + q * 16), Bb + (size_t)(c * 32 + kr) * 16 + q * 4);
            }
        }
        asm volatile("cp.async.commit_group;" ::: "memory");
    };

#pragma unroll
    for (int i = 0; i < 4; ++i) load_chunk(i, i);

    const int arow = lane >> 2, acol = lane & 3;        // fragment lane coords
#pragma unroll 1
    for (int i = 0; i < 64; ++i) {
        int s = i & 3;
        asm volatile("cp.async.wait_group 3;" ::: "memory");
        __syncthreads();
        const float* As = Abase + s * ASTAGEF;
        const float* Bs = Bbase + s * BSTAGEF;
#pragma unroll
        for (int k8 = 0; k8 < 4; ++k8) {
            uint32_t af[2][4];
#pragma unroll
            for (int mi = 0; mi < 2; ++mi) {
                int r = wm * 32 + mi * 16 + arow;
                int c = k8 * 8 + acol;
                af[mi][0] = cvt_tf32(As[r * ASTR + c]);
                af[mi][1] = cvt_tf32(As[(r + 8) * ASTR + c]);
                af[mi][2] = cvt_tf32(As[r * ASTR + c + 4]);
                af[mi][3] = cvt_tf32(As[(r + 8) * ASTR + c + 4]);
            }
            uint32_t bf[NMMA][2];
#pragma unroll
            for (int ni = 0; ni < NMMA; ++ni) {
                int n = wn * (NCOLS / 2) + ni * 8 + arow;
                int kk = k8 * 8 + acol;
                bf[ni][0] = cvt_tf32(Bs[kk * BSTR + n]);
                bf[ni][1] = cvt_tf32(Bs[(kk + 4) * BSTR + n]);
            }
#pragma unroll
            for (int mi = 0; mi < 2; ++mi)
#pragma unroll
                for (int ni = 0; ni < NMMA; ++ni)
                    mma_tf32(acc[mi][ni], af[mi], bf[ni]);
        }
        __syncthreads();
        if (i < 60) load_chunk(i + 4, s);
        else        asm volatile("cp.async.commit_group;" ::: "memory");
    }

    // ---------------- epilogue ----------------
#pragma unroll
    for (int mi = 0; mi < 2; ++mi) {
#pragma unroll
        for (int ni = 0; ni < NMMA; ++ni) {
#pragma unroll
            for (int h = 0; h < 2; ++h) {
                int r = wm * 32 + mi * 16 + arow + h * 8;       // row within 128-tile
                int c = wn * (NCOLS / 2) + ni * 8 + acol * 2;   // col
                float v0 = acc[mi][ni][h * 2 + 0];
                float v1 = acc[mi][ni][h * 2 + 1];
                size_t grow = (size_t)bb * NN + row0 + r;
                if (FINAL) {
                    float dv = g_dinv[grow];
                    float p0 = g_Pp[grow * 16 + c];
                    float p1 = g_Pp[grow * 16 + c + 1];
                    float2 o;
                    o.x = dv * (v0 + p0) + b2[c];
                    o.y = dv * (v1 + p1) + b2[c + 1];
                    *reinterpret_cast<float2*>(out + grow * 16 + c) = o;
                } else {
                    *reinterpret_cast<float2*>(g_T1 + grow * 64 + c) = make_float2(v0, v1);
                }
            }
        }
    }
}

// ---------------- K4: bias+relu+dropout, P' = d*(h@W2) ----------------
__global__ __launch_bounds__(256) void k4_act(const float* __restrict__ b1v,
                                              const float* __restrict__ W2) {
    __shared__ float hs[4][65];
    __shared__ float W2s[64][17];
    int tid = threadIdx.x;
    {
        float4 v = reinterpret_cast<const float4*>(W2)[tid];
        int rr = tid >> 2, c0 = (tid & 3) * 4;
        W2s[rr][c0] = v.x; W2s[rr][c0 + 1] = v.y; W2s[rr][c0 + 2] = v.z; W2s[rr][c0 + 3] = v.w;
    }
    int rl = tid >> 6, t = tid & 63;
    int row = (blockIdx.x << 2) + rl;
    float dv  = g_dinv[row];
    float pre = dv * (g_T1[(size_t)row * 64 + t] + g_M1[(size_t)row * 64 + t]) + b1v[t];
    float h = fmaxf(pre, 0.0f);
    unsigned idx = ((unsigned)row << 6) + (unsigned)t;
    unsigned o0, o1;
    threefry(0u, idx, o0, o1);
    unsigned bits = o0 ^ o1;
    hs[rl][t] = (bits & 0x80000000u) ? 0.0f : h + h;   // keep <=> top bit clear; /0.5 = *2
    __syncthreads();
    if (tid < 64) {
        int rr = tid >> 4, c = tid & 15;
        float acc = 0.0f;
#pragma unroll
        for (int k = 0; k < 64; ++k) acc = fmaf(hs[rr][k], W2s[k][c], acc);
        int grow = (blockIdx.x << 2) + rr;
        g_Pp[(size_t)grow * 16 + c] = g_dinv[grow] * acc;
    }
}

// ---------------- launch ----------------
extern "C" void kernel_launch(void* const* d_in, const int* in_sizes, int n_in,
                              void* d_out, int out_size) {
    const float* X  = (const float*)d_in[0];
    const float* A  = (const float*)d_in[1];
    const float* W1 = (const float*)d_in[2];
    const float* b1 = (const float*)d_in[3];
    const float* W2 = (const float*)d_in[4];
    const float* b2 = (const float*)d_in[5];
    float* out = (float*)d_out;

    const int SM64 = (4 * 128 * 36 + 4 * 32 * 72) * 4;   // 110592 B
    const int SM16 = (4 * 128 * 36 + 4 * 32 * 24) * 4;   //  86016 B
    static int attr_done = 0;
    if (!attr_done) {
        cudaFuncSetAttribute((const void*)gemm_mma<64, false>,
                             cudaFuncAttributeMaxDynamicSharedMemorySize, SM64);
        cudaFuncSetAttribute((const void*)gemm_mma<16, true>,
                             cudaFuncAttributeMaxDynamicSharedMemorySize, SM16);
        attr_done = 1;
    }

    k1_rowsum<<<2048, 256>>>(A);
    k2_xw<<<1024, 256>>>(X, W1);
    gemm_mma<64, false><<<dim3(16, 8), 256, SM64>>>(A, nullptr, nullptr);
    k4_act<<<4096, 256>>>(b1, W2);
    gemm_mma<16, true><<<dim3(16, 8), 256, SM16>>>(A, b2, out);
}

// round 8
// speedup vs baseline: 4.6781x; 1.0659x over previous
#include <cuda_runtime.h>
#include <cuda_bf16.h>
#include <cstdint>
#include <cstddef>

#define NN 2048
#define NROWS 16384   // B * N

// ---------------- device scratch ----------------
__device__ __align__(128) float g_dinv[NROWS];      // rsqrt(rowsum(A)+1)
__device__ __align__(128) float g_M1[NROWS * 64];   // tf32rn(d_j*(X@W1)), row-major
__device__ __align__(128) float g_Pp[NROWS * 16];   // tf32rn(d_j*(h_drop@W2)), row-major

// ---------------- helpers ----------------
__device__ __forceinline__ uint32_t smem_u32(const void* p) {
    uint32_t a;
    asm("{ .reg .u64 t; cvta.to.shared.u64 t, %1; cvt.u32.u64 %0, t; }" : "=r"(a) : "l"(p));
    return a;
}
__device__ __forceinline__ uint32_t cvt_tf32(float f) {
    uint32_t r;
    asm("cvt.rna.tf32.f32 %0, %1;" : "=r"(r) : "f"(f));
    return r;
}
__device__ __forceinline__ float tf32rnf(float f) { return __uint_as_float(cvt_tf32(f)); }
__device__ __forceinline__ void cp16(uint32_t dst, const float* src) {
    asm volatile("cp.async.cg.shared.global [%0], [%1], 16;" :: "r"(dst), "l"(src) : "memory");
}
__device__ __forceinline__ void mma_tf32(float* c, const uint32_t* a, const uint32_t* b) {
    asm volatile("mma.sync.aligned.m16n8k8.row.col.f32.tf32.tf32.f32 "
                 "{%0,%1,%2,%3}, {%4,%5,%6,%7}, {%8,%9}, {%0,%1,%2,%3};"
                 : "+f"(c[0]), "+f"(c[1]), "+f"(c[2]), "+f"(c[3])
                 : "r"(a[0]), "r"(a[1]), "r"(a[2]), "r"(a[3]), "r"(b[0]), "r"(b[1]));
}

// ---------------- exact JAX threefry2x32 (partitionable), key = (0, 42) ----------------
__device__ __forceinline__ unsigned tf_rotl(unsigned x, int r) { return (x << r) | (x >> (32 - r)); }
__device__ __forceinline__ void threefry(unsigned x0, unsigned x1, unsigned &o0, unsigned &o1) {
    const unsigned k0 = 0u, k1 = 42u;
    const unsigned k2 = 0x1BD11BDAu ^ k0 ^ k1;
    x0 += k0; x1 += k1;
#define RND(r) { x0 += x1; x1 = tf_rotl(x1, (r)); x1 ^= x0; }
    RND(13) RND(15) RND(26) RND(6)   x0 += k1; x1 += k2 + 1u;
    RND(17) RND(29) RND(16) RND(24)  x0 += k2; x1 += k0 + 2u;
    RND(13) RND(15) RND(26) RND(6)   x0 += k0; x1 += k1 + 3u;
    RND(17) RND(29) RND(16) RND(24)  x0 += k1; x1 += k2 + 4u;
    RND(13) RND(15) RND(26) RND(6)   x0 += k2; x1 += k0 + 5u;
#undef RND
    o0 = x0; o1 = x1;
}

// ---------------- K1: d = rsqrt(rowsum(A)+1), one warp per row ----------------
__global__ __launch_bounds__(256) void k1_rowsum(const float* __restrict__ A) {
    int row  = blockIdx.x * 8 + (threadIdx.x >> 5);
    int lane = threadIdx.x & 31;
    const float4* p = reinterpret_cast<const float4*>(A + (size_t)row * NN);
    float s0 = 0.f, s1 = 0.f, s2 = 0.f, s3 = 0.f;
#pragma unroll
    for (int it = 0; it < 16; it += 4) {
        float4 a = p[(it + 0) * 32 + lane];
        float4 b = p[(it + 1) * 32 + lane];
        float4 c = p[(it + 2) * 32 + lane];
        float4 d = p[(it + 3) * 32 + lane];
        s0 += (a.x + a.y) + (a.z + a.w);
        s1 += (b.x + b.y) + (b.z + b.w);
        s2 += (c.x + c.y) + (c.z + c.w);
        s3 += (d.x + d.y) + (d.z + d.w);
    }
    float s = (s0 + s1) + (s2 + s3);
#pragma unroll
    for (int o = 16; o; o >>= 1) s += __shfl_xor_sync(0xffffffffu, s, o);
    if (lane == 0) g_dinv[row] = rsqrtf(s + 1.0f);
}

// ---------------- K2: M1 = tf32rn(d * (X @ W1)) ----------------
__global__ __launch_bounds__(256) void k2_xw(const float* __restrict__ X,
                                             const float* __restrict__ W1) {
    __shared__ __align__(16) float Ws[64][64];
    __shared__ float Xs[16][68];
    int tid  = threadIdx.x;
    int row0 = blockIdx.x * 16;
#pragma unroll
    for (int s = 0; s < 4; ++s) {
        int slot = tid + s * 256;
        *reinterpret_cast<float4*>(&Ws[0][0] + (size_t)slot * 4) =
            reinterpret_cast<const float4*>(W1)[slot];
    }
    {
        int r = tid >> 4, cq = tid & 15;
        float4 v = reinterpret_cast<const float4*>(X + (size_t)(row0 + r) * 64)[cq];
        Xs[r][cq * 4 + 0] = v.x; Xs[r][cq * 4 + 1] = v.y;
        Xs[r][cq * 4 + 2] = v.z; Xs[r][cq * 4 + 3] = v.w;
    }
    __syncthreads();
    int r = tid >> 4, cx = tid & 15;
    float4 acc = make_float4(0.f, 0.f, 0.f, 0.f);
#pragma unroll
    for (int k = 0; k < 64; ++k) {
        float x  = Xs[r][k];
        float4 w = *reinterpret_cast<const float4*>(&Ws[k][cx * 4]);
        acc.x = fmaf(x, w.x, acc.x);
        acc.y = fmaf(x, w.y, acc.y);
        acc.z = fmaf(x, w.z, acc.z);
        acc.w = fmaf(x, w.w, acc.w);
    }
    int grow = row0 + r;
    float d  = g_dinv[grow];
    acc.x = tf32rnf(acc.x * d); acc.y = tf32rnf(acc.y * d);
    acc.z = tf32rnf(acc.z * d); acc.w = tf32rnf(acc.w * d);
    reinterpret_cast<float4*>(g_M1 + (size_t)grow * 64)[cx] = acc;
}

// ---------------- tf32 mma.sync GEMM with fused epilogues ----------------
// NCOLS=64, FINAL=false: B=g_M1 (pre-rounded tf32); fused epilogue computes
//   h=relu(d*(acc+M1)+b1), threefry dropout, Pp = tf32rn(d*(h@W2)) -> g_Pp.
// NCOLS=16, FINAL=true : B=g_Pp (pre-rounded); epilogue out = d*(acc+Pp)+b2 -> out.
template<int NCOLS, bool FINAL>
__global__ __launch_bounds__(256) void gemm_mma(const float* __restrict__ A,
                                                const float* __restrict__ b1g,
                                                const float* __restrict__ W2g,
                                                const float* __restrict__ b2,
                                                float* __restrict__ out) {
    constexpr int ASTR = 36;                      // A smem stride (floats)
    constexpr int BSTR = (NCOLS == 64) ? 72 : 24; // B smem stride (floats)
    constexpr int ASTAGEF = 128 * ASTR;           // 4608 floats per stage
    constexpr int BSTAGEF = 32 * BSTR;
    extern __shared__ __align__(16) float smem[];
    float* Abase = smem;
    float* Bbase = smem + 4 * ASTAGEF;

    const int tid = threadIdx.x, wid = tid >> 5, lane = tid & 31;
    const int wm = wid & 3, wn = wid >> 2;              // warp tile rows wm*32, cols wn*(NCOLS/2)
    const int bb = blockIdx.y, row0 = blockIdx.x << 7;
    const float* Ab = A + ((size_t)bb * NN + row0) * NN;
    const float* Bb = (FINAL ? g_Pp : g_M1) + (size_t)bb * NN * NCOLS;
    const uint32_t sb = smem_u32(smem);

    constexpr int NMMA = (NCOLS == 64) ? 4 : 1;
    float acc[2][NMMA][4];
#pragma unroll
    for (int i = 0; i < 2; ++i)
#pragma unroll
        for (int j = 0; j < NMMA; ++j)
#pragma unroll
            for (int q = 0; q < 4; ++q) acc[i][j][q] = 0.f;

    auto load_chunk = [&](int c, int s) {
        uint32_t ab = sb + s * (ASTAGEF * 4);
#pragma unroll
        for (int j = 0; j < 4; ++j) {
            int seg = tid + j * 256;
            int r = seg >> 3, q = seg & 7;
            cp16(ab + (uint32_t)(r * ASTR * 4 + q * 16), Ab + (size_t)r * NN + c * 32 + q * 4);
        }
        uint32_t bbs = sb + (uint32_t)(4 * ASTAGEF * 4) + s * (BSTAGEF * 4);
        if (NCOLS == 64) {
#pragma unroll
            for (int j = 0; j < 2; ++j) {
                int seg = tid + j * 256;
                int kr = seg >> 4, q = seg & 15;
                cp16(bbs + (uint32_t)(kr * BSTR * 4 + q * 16), Bb + (size_t)(c * 32 + kr) * 64 + q * 4);
            }
        } else {
            if (tid < 128) {
                int kr = tid >> 2, q = tid & 3;
                cp16(bbs + (uint32_t)(kr * BSTR * 4 + q * 16), Bb + (size_t)(c * 32 + kr) * 16 + q * 4);
            }
        }
        asm volatile("cp.async.commit_group;" ::: "memory");
    };

    // prologue: 3 chunks ahead
    load_chunk(0, 0); load_chunk(1, 1); load_chunk(2, 2);

    const int arow = lane >> 2, acol = lane & 3;
#pragma unroll 1
    for (int i = 0; i < 64; ++i) {
        int s = i & 3;
        asm volatile("cp.async.wait_group 2;" ::: "memory");   // chunk i resident
        __syncthreads();                                       // all warps done with stage (i-1)&3
        if (i < 61) load_chunk(i + 3, (i + 3) & 3);            // overlap load with compute
        else        asm volatile("cp.async.commit_group;" ::: "memory");
        const float* As = Abase + s * ASTAGEF;
        const float* Bs = Bbase + s * BSTAGEF;
#pragma unroll
        for (int k8 = 0; k8 < 4; ++k8) {
            uint32_t af[2][4];
#pragma unroll
            for (int mi = 0; mi < 2; ++mi) {
                int r = wm * 32 + mi * 16 + arow;
                int c = k8 * 8 + acol;
                af[mi][0] = cvt_tf32(As[r * ASTR + c]);
                af[mi][1] = cvt_tf32(As[(r + 8) * ASTR + c]);
                af[mi][2] = cvt_tf32(As[r * ASTR + c + 4]);
                af[mi][3] = cvt_tf32(As[(r + 8) * ASTR + c + 4]);
            }
            uint32_t bf[NMMA][2];
#pragma unroll
            for (int ni = 0; ni < NMMA; ++ni) {
                int n = wn * (NCOLS / 2) + ni * 8 + arow;
                int kk = k8 * 8 + acol;
                bf[ni][0] = __float_as_uint(Bs[kk * BSTR + n]);   // pre-rounded in producer
                bf[ni][1] = __float_as_uint(Bs[(kk + 4) * BSTR + n]);
            }
#pragma unroll
            for (int mi = 0; mi < 2; ++mi)
#pragma unroll
                for (int ni = 0; ni < NMMA; ++ni)
                    mma_tf32(acc[mi][ni], af[mi], bf[ni]);
        }
    }

    // ---------------- epilogues ----------------
    if (FINAL) {
#pragma unroll
        for (int mi = 0; mi < 2; ++mi) {
#pragma unroll
            for (int ni = 0; ni < NMMA; ++ni) {
#pragma unroll
                for (int h = 0; h < 2; ++h) {
                    int r = wm * 32 + mi * 16 + arow + h * 8;
                    int c = wn * (NCOLS / 2) + ni * 8 + acol * 2;
                    float v0 = acc[mi][ni][h * 2 + 0];
                    float v1 = acc[mi][ni][h * 2 + 1];
                    size_t grow = (size_t)bb * NN + row0 + r;
                    float dv = g_dinv[grow];
                    float p0 = g_Pp[grow * 16 + c];
                    float p1 = g_Pp[grow * 16 + c + 1];
                    float2 o;
                    o.x = dv * (v0 + p0) + b2[c];
                    o.y = dv * (v1 + p1) + b2[c + 1];
                    *reinterpret_cast<float2*>(out + grow * 16 + c) = o;
                }
            }
        }
    } else {
        // fused layer-1 activation + dropout + (h @ W2) epilogue
        constexpr int HSTR = 66;
        float* hs  = smem;                    // [128][66] (reuses pipeline smem)
        float* W2s = smem + 128 * HSTR;       // [64][16]
        __syncthreads();                      // pipeline reads fully done before overwrite
        reinterpret_cast<float4*>(W2s)[tid] = reinterpret_cast<const float4*>(W2g)[tid]; // 1024 floats
#pragma unroll
        for (int mi = 0; mi < 2; ++mi) {
#pragma unroll
            for (int h = 0; h < 2; ++h) {
                int r = wm * 32 + mi * 16 + arow + h * 8;
                size_t grow = (size_t)bb * NN + row0 + r;
                float dv = g_dinv[grow];
#pragma unroll
                for (int ni = 0; ni < NMMA; ++ni) {
                    int c = wn * 32 + ni * 8 + acol * 2;
#pragma unroll
                    for (int e = 0; e < 2; ++e) {
                        float val = acc[mi][ni][h * 2 + e];
                        float pre = dv * (val + g_M1[grow * 64 + c + e]) + b1g[c + e];
                        float hh  = fmaxf(pre, 0.0f);
                        unsigned idx = ((unsigned)grow << 6) + (unsigned)(c + e);
                        unsigned o0, o1;
                        threefry(0u, idx, o0, o1);
                        hs[r * HSTR + c + e] = ((o0 ^ o1) & 0x80000000u) ? 0.0f : hh + hh;
                    }
                }
            }
        }
        __syncthreads();
        // Pp = tf32rn(dinv * (hs @ W2)): thread -> (row = tid>>1, 8 cols)
        int r2 = tid >> 1, cg = (tid & 1) * 8;
        float a8[8] = {0.f, 0.f, 0.f, 0.f, 0.f, 0.f, 0.f, 0.f};
#pragma unroll
        for (int k = 0; k < 64; ++k) {
            float hv = hs[r2 * HSTR + k];
            float4 w0 = *reinterpret_cast<const float4*>(&W2s[k * 16 + cg]);
            float4 w1 = *reinterpret_cast<const float4*>(&W2s[k * 16 + cg + 4]);
            a8[0] = fmaf(hv, w0.x, a8[0]); a8[1] = fmaf(hv, w0.y, a8[1]);
            a8[2] = fmaf(hv, w0.z, a8[2]); a8[3] = fmaf(hv, w0.w, a8[3]);
            a8[4] = fmaf(hv, w1.x, a8[4]); a8[5] = fmaf(hv, w1.y, a8[5]);
            a8[6] = fmaf(hv, w1.z, a8[6]); a8[7] = fmaf(hv, w1.w, a8[7]);
        }
        size_t grow2 = (size_t)bb * NN + row0 + r2;
        float dv2 = g_dinv[grow2];
        float4 s0 = make_float4(tf32rnf(a8[0] * dv2), tf32rnf(a8[1] * dv2),
                                tf32rnf(a8[2] * dv2), tf32rnf(a8[3] * dv2));
        float4 s1 = make_float4(tf32rnf(a8[4] * dv2), tf32rnf(a8[5] * dv2),
                                tf32rnf(a8[6] * dv2), tf32rnf(a8[7] * dv2));
        reinterpret_cast<float4*>(&g_Pp[grow2 * 16 + cg])[0] = s0;
        reinterpret_cast<float4*>(&g_Pp[grow2 * 16 + cg + 4])[0] = s1;
    }
}

// ---------------- launch ----------------
extern "C" void kernel_launch(void* const* d_in, const int* in_sizes, int n_in,
                              void* d_out, int out_size) {
    const float* X  = (const float*)d_in[0];
    const float* A  = (const float*)d_in[1];
    const float* W1 = (const float*)d_in[2];
    const float* b1 = (const float*)d_in[3];
    const float* W2 = (const float*)d_in[4];
    const float* b2 = (const float*)d_in[5];
    float* out = (float*)d_out;

    const int SM64 = (4 * 128 * 36 + 4 * 32 * 72) * 4;   // 110592 B (covers epilogue reuse too)
    const int SM16 = (4 * 128 * 36 + 4 * 32 * 24) * 4;   //  86016 B
    static int attr_done = 0;
    if (!attr_done) {
        cudaFuncSetAttribute((const void*)gemm_mma<64, false>,
                             cudaFuncAttributeMaxDynamicSharedMemorySize, SM64);
        cudaFuncSetAttribute((const void*)gemm_mma<16, true>,
                             cudaFuncAttributeMaxDynamicSharedMemorySize, SM16);
        attr_done = 1;
    }

    k1_rowsum<<<2048, 256>>>(A);
    k2_xw<<<1024, 256>>>(X, W1);
    gemm_mma<64, false><<<dim3(16, 8), 256, SM64>>>(A, b1, W2, nullptr, nullptr);
    gemm_mma<16, true><<<dim3(16, 8), 256, SM16>>>(A, nullptr, nullptr, b2, out);
}

// round 9
// speedup vs baseline: 4.8549x; 1.0378x over previous
#include <cuda_runtime.h>
#include <cuda_bf16.h>
#include <cstdint>
#include <cstddef>

#define NN 2048
#define NROWS 16384   // B * N

// ---------------- device scratch ----------------
__device__ __align__(128) float g_dinv[NROWS];      // rsqrt(rowsum(A)+1)
__device__ __align__(128) float g_M1[NROWS * 64];   // tf32rn(d_j*(X@W1)), row-major
__device__ __align__(128) float g_Pp[NROWS * 16];   // tf32rn(d_j*(h_drop@W2)), row-major

// ---------------- helpers ----------------
__device__ __forceinline__ uint32_t smem_u32(const void* p) {
    uint32_t a;
    asm("{ .reg .u64 t; cvta.to.shared.u64 t, %1; cvt.u32.u64 %0, t; }" : "=r"(a) : "l"(p));
    return a;
}
__device__ __forceinline__ uint32_t cvt_tf32(float f) {
    uint32_t r;
    asm("cvt.rna.tf32.f32 %0, %1;" : "=r"(r) : "f"(f));
    return r;
}
__device__ __forceinline__ float tf32rnf(float f) { return __uint_as_float(cvt_tf32(f)); }
__device__ __forceinline__ void cp16(uint32_t dst, const float* src) {
    asm volatile("cp.async.cg.shared.global [%0], [%1], 16;" :: "r"(dst), "l"(src) : "memory");
}
__device__ __forceinline__ void mma_tf32(float* c, const uint32_t* a, const uint32_t* b) {
    asm volatile("mma.sync.aligned.m16n8k8.row.col.f32.tf32.tf32.f32 "
                 "{%0,%1,%2,%3}, {%4,%5,%6,%7}, {%8,%9}, {%0,%1,%2,%3};"
                 : "+f"(c[0]), "+f"(c[1]), "+f"(c[2]), "+f"(c[3])
                 : "r"(a[0]), "r"(a[1]), "r"(a[2]), "r"(a[3]), "r"(b[0]), "r"(b[1]));
}

// ---------------- exact JAX threefry2x32 (partitionable), key = (0, 42) ----------------
__device__ __forceinline__ unsigned tf_rotl(unsigned x, int r) { return (x << r) | (x >> (32 - r)); }
__device__ __forceinline__ void threefry(unsigned x0, unsigned x1, unsigned &o0, unsigned &o1) {
    const unsigned k0 = 0u, k1 = 42u;
    const unsigned k2 = 0x1BD11BDAu ^ k0 ^ k1;
    x0 += k0; x1 += k1;
#define RND(r) { x0 += x1; x1 = tf_rotl(x1, (r)); x1 ^= x0; }
    RND(13) RND(15) RND(26) RND(6)   x0 += k1; x1 += k2 + 1u;
    RND(17) RND(29) RND(16) RND(24)  x0 += k2; x1 += k0 + 2u;
    RND(13) RND(15) RND(26) RND(6)   x0 += k0; x1 += k1 + 3u;
    RND(17) RND(29) RND(16) RND(24)  x0 += k1; x1 += k2 + 4u;
    RND(13) RND(15) RND(26) RND(6)   x0 += k2; x1 += k0 + 5u;
#undef RND
    o0 = x0; o1 = x1;
}

// ---------------- K1: d = rsqrt(rowsum(A)+1), one warp per row ----------------
__global__ __launch_bounds__(256) void k1_rowsum(const float* __restrict__ A) {
    int row  = blockIdx.x * 8 + (threadIdx.x >> 5);
    int lane = threadIdx.x & 31;
    const float4* p = reinterpret_cast<const float4*>(A + (size_t)row * NN);
    float s0 = 0.f, s1 = 0.f, s2 = 0.f, s3 = 0.f;
#pragma unroll
    for (int it = 0; it < 16; it += 4) {
        float4 a = p[(it + 0) * 32 + lane];
        float4 b = p[(it + 1) * 32 + lane];
        float4 c = p[(it + 2) * 32 + lane];
        float4 d = p[(it + 3) * 32 + lane];
        s0 += (a.x + a.y) + (a.z + a.w);
        s1 += (b.x + b.y) + (b.z + b.w);
        s2 += (c.x + c.y) + (c.z + c.w);
        s3 += (d.x + d.y) + (d.z + d.w);
    }
    float s = (s0 + s1) + (s2 + s3);
#pragma unroll
    for (int o = 16; o; o >>= 1) s += __shfl_xor_sync(0xffffffffu, s, o);
    if (lane == 0) g_dinv[row] = rsqrtf(s + 1.0f);
}

// ---------------- K2: M1 = tf32rn(d * (X @ W1)) ----------------
__global__ __launch_bounds__(256) void k2_xw(const float* __restrict__ X,
                                             const float* __restrict__ W1) {
    __shared__ __align__(16) float Ws[64][64];
    __shared__ float Xs[16][68];
    int tid  = threadIdx.x;
    int row0 = blockIdx.x * 16;
#pragma unroll
    for (int s = 0; s < 4; ++s) {
        int slot = tid + s * 256;
        *reinterpret_cast<float4*>(&Ws[0][0] + (size_t)slot * 4) =
            reinterpret_cast<const float4*>(W1)[slot];
    }
    {
        int r = tid >> 4, cq = tid & 15;
        float4 v = reinterpret_cast<const float4*>(X + (size_t)(row0 + r) * 64)[cq];
        Xs[r][cq * 4 + 0] = v.x; Xs[r][cq * 4 + 1] = v.y;
        Xs[r][cq * 4 + 2] = v.z; Xs[r][cq * 4 + 3] = v.w;
    }
    __syncthreads();
    int r = tid >> 4, cx = tid & 15;
    float4 acc = make_float4(0.f, 0.f, 0.f, 0.f);
#pragma unroll
    for (int k = 0; k < 64; ++k) {
        float x  = Xs[r][k];
        float4 w = *reinterpret_cast<const float4*>(&Ws[k][cx * 4]);
        acc.x = fmaf(x, w.x, acc.x);
        acc.y = fmaf(x, w.y, acc.y);
        acc.z = fmaf(x, w.z, acc.z);
        acc.w = fmaf(x, w.w, acc.w);
    }
    int grow = row0 + r;
    float d  = g_dinv[grow];
    acc.x = tf32rnf(acc.x * d); acc.y = tf32rnf(acc.y * d);
    acc.z = tf32rnf(acc.z * d); acc.w = tf32rnf(acc.w * d);
    reinterpret_cast<float4*>(g_M1 + (size_t)grow * 64)[cx] = acc;
}

// ---------------- tf32 mma.sync GEMM, 8-stage cp.async pipeline, fused epilogues ----------------
// NCOLS=64, FINAL=false: B=g_M1 (pre-rounded tf32); fused epilogue computes
//   h=relu(d*(acc+M1)+b1), threefry dropout, Pp = tf32rn(d*(h@W2)) -> g_Pp.
// NCOLS=16, FINAL=true : B=g_Pp (pre-rounded); epilogue out = d*(acc+Pp)+b2 -> out.
template<int NCOLS, bool FINAL>
__global__ __launch_bounds__(256) void gemm_mma(const float* __restrict__ A,
                                                const float* __restrict__ b1g,
                                                const float* __restrict__ W2g,
                                                const float* __restrict__ b2,
                                                float* __restrict__ out) {
    constexpr int NSTAGE = 8;
    constexpr int ASTR = 36;                      // A smem stride (floats)
    constexpr int BSTR = (NCOLS == 64) ? 72 : 24; // B smem stride (floats)
    constexpr int ASTAGEF = 128 * ASTR;           // 4608 floats per stage
    constexpr int BSTAGEF = 32 * BSTR;
    extern __shared__ __align__(16) float smem[];
    float* Abase = smem;
    float* Bbase = smem + NSTAGE * ASTAGEF;

    const int tid = threadIdx.x, wid = tid >> 5, lane = tid & 31;
    const int wm = wid & 3, wn = wid >> 2;              // warp tile rows wm*32, cols wn*(NCOLS/2)
    const int bb = blockIdx.y, row0 = blockIdx.x << 7;
    const float* Ab = A + ((size_t)bb * NN + row0) * NN;
    const float* Bb = (FINAL ? g_Pp : g_M1) + (size_t)bb * NN * NCOLS;
    const uint32_t sb = smem_u32(smem);

    constexpr int NMMA = (NCOLS == 64) ? 4 : 1;
    float acc[2][NMMA][4];
#pragma unroll
    for (int i = 0; i < 2; ++i)
#pragma unroll
        for (int j = 0; j < NMMA; ++j)
#pragma unroll
            for (int q = 0; q < 4; ++q) acc[i][j][q] = 0.f;

    auto load_chunk = [&](int c, int s) {
        uint32_t ab = sb + s * (ASTAGEF * 4);
#pragma unroll
        for (int j = 0; j < 4; ++j) {
            int seg = tid + j * 256;
            int r = seg >> 3, q = seg & 7;
            cp16(ab + (uint32_t)(r * ASTR * 4 + q * 16), Ab + (size_t)r * NN + c * 32 + q * 4);
        }
        uint32_t bbs = sb + (uint32_t)(NSTAGE * ASTAGEF * 4) + s * (BSTAGEF * 4);
        if (NCOLS == 64) {
#pragma unroll
            for (int j = 0; j < 2; ++j) {
                int seg = tid + j * 256;
                int kr = seg >> 4, q = seg & 15;
                cp16(bbs + (uint32_t)(kr * BSTR * 4 + q * 16), Bb + (size_t)(c * 32 + kr) * 64 + q * 4);
            }
        } else {
            if (tid < 128) {
                int kr = tid >> 2, q = tid & 3;
                cp16(bbs + (uint32_t)(kr * BSTR * 4 + q * 16), Bb + (size_t)(c * 32 + kr) * 16 + q * 4);
            }
        }
        asm volatile("cp.async.commit_group;" ::: "memory");
    };

    // prologue: 7 chunks ahead
#pragma unroll
    for (int c = 0; c < 7; ++c) load_chunk(c, c);

    const int arow = lane >> 2, acol = lane & 3;
#pragma unroll 1
    for (int i = 0; i < 64; ++i) {
        int s = i & (NSTAGE - 1);
        asm volatile("cp.async.wait_group 6;" ::: "memory");   // chunk i resident
        __syncthreads();                                       // all warps done with stage (i-1)
        if (i < 57) load_chunk(i + 7, (i + 7) & (NSTAGE - 1)); // overlap load with compute
        else        asm volatile("cp.async.commit_group;" ::: "memory");
        const float* As = Abase + s * ASTAGEF;
        const float* Bs = Bbase + s * BSTAGEF;
#pragma unroll
        for (int k8 = 0; k8 < 4; ++k8) {
            uint32_t af[2][4];
#pragma unroll
            for (int mi = 0; mi < 2; ++mi) {
                int r = wm * 32 + mi * 16 + arow;
                int c = k8 * 8 + acol;
                af[mi][0] = cvt_tf32(As[r * ASTR + c]);
                af[mi][1] = cvt_tf32(As[(r + 8) * ASTR + c]);
                af[mi][2] = cvt_tf32(As[r * ASTR + c + 4]);
                af[mi][3] = cvt_tf32(As[(r + 8) * ASTR + c + 4]);
            }
            uint32_t bf[NMMA][2];
#pragma unroll
            for (int ni = 0; ni < NMMA; ++ni) {
                int n = wn * (NCOLS / 2) + ni * 8 + arow;
                int kk = k8 * 8 + acol;
                bf[ni][0] = __float_as_uint(Bs[kk * BSTR + n]);   // pre-rounded in producer
                bf[ni][1] = __float_as_uint(Bs[(kk + 4) * BSTR + n]);
            }
#pragma unroll
            for (int mi = 0; mi < 2; ++mi)
#pragma unroll
                for (int ni = 0; ni < NMMA; ++ni)
                    mma_tf32(acc[mi][ni], af[mi], bf[ni]);
        }
    }

    // ---------------- epilogues ----------------
    if (FINAL) {
#pragma unroll
        for (int mi = 0; mi < 2; ++mi) {
#pragma unroll
            for (int ni = 0; ni < NMMA; ++ni) {
#pragma unroll
                for (int h = 0; h < 2; ++h) {
                    int r = wm * 32 + mi * 16 + arow + h * 8;
                    int c = wn * (NCOLS / 2) + ni * 8 + acol * 2;
                    float v0 = acc[mi][ni][h * 2 + 0];
                    float v1 = acc[mi][ni][h * 2 + 1];
                    size_t grow = (size_t)bb * NN + row0 + r;
                    float dv = g_dinv[grow];
                    float p0 = g_Pp[grow * 16 + c];
                    float p1 = g_Pp[grow * 16 + c + 1];
                    float2 o;
                    o.x = dv * (v0 + p0) + b2[c];
                    o.y = dv * (v1 + p1) + b2[c + 1];
                    *reinterpret_cast<float2*>(out + grow * 16 + c) = o;
                }
            }
        }
    } else {
        // fused layer-1 activation + dropout + (h @ W2) epilogue
        constexpr int HSTR = 66;
        float* hs  = smem;                    // [128][66] (reuses pipeline smem)
        float* W2s = smem + 128 * HSTR;       // [64][16]
        __syncthreads();                      // pipeline reads fully done before overwrite
        reinterpret_cast<float4*>(W2s)[tid] = reinterpret_cast<const float4*>(W2g)[tid]; // 1024 floats
#pragma unroll
        for (int mi = 0; mi < 2; ++mi) {
#pragma unroll
            for (int h = 0; h < 2; ++h) {
                int r = wm * 32 + mi * 16 + arow + h * 8;
                size_t grow = (size_t)bb * NN + row0 + r;
                float dv = g_dinv[grow];
#pragma unroll
                for (int ni = 0; ni < NMMA; ++ni) {
                    int c = wn * 32 + ni * 8 + acol * 2;
#pragma unroll
                    for (int e = 0; e < 2; ++e) {
                        float val = acc[mi][ni][h * 2 + e];
                        float pre = dv * (val + g_M1[grow * 64 + c + e]) + b1g[c + e];
                        float hh  = fmaxf(pre, 0.0f);
                        unsigned idx = ((unsigned)grow << 6) + (unsigned)(c + e);
                        unsigned o0, o1;
                        threefry(0u, idx, o0, o1);
                        hs[r * HSTR + c + e] = ((o0 ^ o1) & 0x80000000u) ? 0.0f : hh + hh;
                    }
                }
            }
        }
        __syncthreads();
        // Pp = tf32rn(dinv * (hs @ W2)): thread -> (row = tid>>1, 8 cols)
        int r2 = tid >> 1, cg = (tid & 1) * 8;
        float a8[8] = {0.f, 0.f, 0.f, 0.f, 0.f, 0.f, 0.f, 0.f};
#pragma unroll
        for (int k = 0; k < 64; ++k) {
            float hv = hs[r2 * HSTR + k];
            float4 w0 = *reinterpret_cast<const float4*>(&W2s[k * 16 + cg]);
            float4 w1 = *reinterpret_cast<const float4*>(&W2s[k * 16 + cg + 4]);
            a8[0] = fmaf(hv, w0.x, a8[0]); a8[1] = fmaf(hv, w0.y, a8[1]);
            a8[2] = fmaf(hv, w0.z, a8[2]); a8[3] = fmaf(hv, w0.w, a8[3]);
            a8[4] = fmaf(hv, w1.x, a8[4]); a8[5] = fmaf(hv, w1.y, a8[5]);
            a8[6] = fmaf(hv, w1.z, a8[6]); a8[7] = fmaf(hv, w1.w, a8[7]);
        }
        size_t grow2 = (size_t)bb * NN + row0 + r2;
        float dv2 = g_dinv[grow2];
        float4 s0 = make_float4(tf32rnf(a8[0] * dv2), tf32rnf(a8[1] * dv2),
                                tf32rnf(a8[2] * dv2), tf32rnf(a8[3] * dv2));
        float4 s1 = make_float4(tf32rnf(a8[4] * dv2), tf32rnf(a8[5] * dv2),
                                tf32rnf(a8[6] * dv2), tf32rnf(a8[7] * dv2));
        reinterpret_cast<float4*>(&g_Pp[grow2 * 16 + cg])[0] = s0;
        reinterpret_cast<float4*>(&g_Pp[grow2 * 16 + cg + 4])[0] = s1;
    }
}

// ---------------- launch ----------------
extern "C" void kernel_launch(void* const* d_in, const int* in_sizes, int n_in,
                              void* d_out, int out_size) {
    const float* X  = (const float*)d_in[0];
    const float* A  = (const float*)d_in[1];
    const float* W1 = (const float*)d_in[2];
    const float* b1 = (const float*)d_in[3];
    const float* W2 = (const float*)d_in[4];
    const float* b2 = (const float*)d_in[5];
    float* out = (float*)d_out;

    const int SM64 = (8 * 128 * 36 + 8 * 32 * 72) * 4;   // 221184 B
    const int SM16 = (8 * 128 * 36 + 8 * 32 * 24) * 4;   // 172032 B
    static int attr_done = 0;
    if (!attr_done) {
        cudaFuncSetAttribute((const void*)gemm_mma<64, false>,
                             cudaFuncAttributeMaxDynamicSharedMemorySize, SM64);
        cudaFuncSetAttribute((const void*)gemm_mma<16, true>,
                             cudaFuncAttributeMaxDynamicSharedMemorySize, SM16);
        attr_done = 1;
    }

    k1_rowsum<<<2048, 256>>>(A);
    k2_xw<<<1024, 256>>>(X, W1);
    gemm_mma<64, false><<<dim3(16, 8), 256, SM64>>>(A, b1, W2, nullptr, nullptr);
    gemm_mma<16, true><<<dim3(16, 8), 256, SM16>>>(A, nullptr, nullptr, b2, out);
}